// round 14
// baseline (speedup 1.0000x reference)
#include <cuda_runtime.h>
#include <cstdint>

// Reference: LATENT_DIM=16, N_PARAMS=2, POLY_ORDER=3
#define NVARS   18
#define NPAIRS  9
#define BATCH_N 131072
#define TPB     128
#define RPT     2             // batch rows per thread (amortize weight fetch)
#define WROW_B  80            // padded weight row: 10 u64 = 80 bytes

typedef unsigned long long u64;
typedef unsigned int u32;

__device__ __forceinline__ u64 ffma2(u64 a, u64 b, u64 c) {
    u64 d;
    asm("fma.rn.f32x2 %0, %1, %2, %3;" : "=l"(d) : "l"(a), "l"(b), "l"(c));
    return d;
}
__device__ __forceinline__ u64 fadd2(u64 a, u64 b) {
    u64 d;
    asm("add.rn.f32x2 %0, %1, %2;" : "=l"(d) : "l"(a), "l"(b));
    return d;
}
__device__ __forceinline__ u64 pack2(float lo, float hi) {
    u64 d;
    asm("mov.b64 %0, {%1, %2};" : "=l"(d) : "f"(lo), "f"(hi));
    return d;
}
__device__ __forceinline__ u64 dup2(float v) { return pack2(v, v); }

// Weight row: 4x LDS.128 + 1x LDS.64 (u32 shared addr + imm offsets).
__device__ __forceinline__ void load_wrow(u32 a, u64 wp[NPAIRS]) {
    asm("ld.shared.v2.u64 {%0, %1}, [%2];"    : "=l"(wp[0]), "=l"(wp[1]) : "r"(a));
    asm("ld.shared.v2.u64 {%0, %1}, [%2+16];" : "=l"(wp[2]), "=l"(wp[3]) : "r"(a));
    asm("ld.shared.v2.u64 {%0, %1}, [%2+32];" : "=l"(wp[4]), "=l"(wp[5]) : "r"(a));
    asm("ld.shared.v2.u64 {%0, %1}, [%2+48];" : "=l"(wp[6]), "=l"(wp[7]) : "r"(a));
    asm("ld.shared.u64 %0, [%1+64];"          : "=l"(wp[8])              : "r"(a));
}

// One split-K piece over outer monomial index a in [A0, A1).
// N1/N2/N3: per-degree row counts of this piece; G1/G2/G3: global row starts.
template<int A0, int A1, int N1, int N2, int N3, int G1, int G2, int G3,
         bool HASBIAS, bool STORE_DIRECT>
__global__ void __launch_bounds__(TPB, 6)
vindy_piece(const float* __restrict__ z,
            const float* __restrict__ betas,
            const float* __restrict__ big_xi,
            const float* __restrict__ mask,
            float* __restrict__ out)
{
    constexpr int NR = 1 + N1 + N2 + N3;     // local row 0 = bias (or zeros)
    extern __shared__ __align__(16) u64 Wsh[];

    const int tid = threadIdx.x;

    // Stage this piece's weight rows (3 contiguous global ranges) + bias slot.
    for (int i = tid; i < NR * NPAIRS; i += TPB) {
        const int l = i / NPAIRS, p = i % NPAIRS;
        int g;
        if (l == 0)                 g = HASBIAS ? 0 : -1;
        else if (l < 1 + N1)        g = G1 + (l - 1);
        else if (l < 1 + N1 + N2)   g = G2 + (l - 1 - N1);
        else                        g = G3 + (l - 1 - N1 - N2);
        u64 v = 0;
        if (g >= 0) {
            const int gg = g * NVARS + 2 * p;
            v = pack2(big_xi[gg] * mask[gg], big_xi[gg + 1] * mask[gg + 1]);
        }
        Wsh[l * (WROW_B / 8) + p] = v;
    }

    const int base = (blockIdx.x * TPB + tid) * RPT;

    // x = concat(z, betas) per row; dynamic index -> local mem (144 B).
    float xs[RPT][NVARS];
    #pragma unroll
    for (int r = 0; r < RPT; ++r) {
        const int row = base + r;
        const float4* zp = reinterpret_cast<const float4*>(z + (size_t)row * 16);
        #pragma unroll
        for (int q = 0; q < 4; ++q) {
            const float4 v = zp[q];
            xs[r][q * 4 + 0] = v.x;
            xs[r][q * 4 + 1] = v.y;
            xs[r][q * 4 + 2] = v.z;
            xs[r][q * 4 + 3] = v.w;
        }
        const float2 bt = reinterpret_cast<const float2*>(betas)[row];
        xs[r][16] = bt.x;
        xs[r][17] = bt.y;
    }

    __syncthreads();

    const u32 sb = (u32)__cvta_generic_to_shared(Wsh);
    u32 c1 = sb + 1 * WROW_B;
    u32 c2 = sb + (1 + N1) * WROW_B;
    u32 c3 = sb + (1 + N1 + N2) * WROW_B;

    // acc[r][p] = (out[2p], out[2p+1]); init = bias row (zeros off-bias piece)
    u64 acc[RPT][NPAIRS];
    {
        u64 wb[NPAIRS];
        load_wrow(sb, wb);
        #pragma unroll
        for (int r = 0; r < RPT; ++r)
            #pragma unroll
            for (int p = 0; p < NPAIRS; ++p) acc[r][p] = wb[p];
    }

    #pragma unroll 1
    for (int a = A0; a < A1; ++a) {
        float xa[RPT];
        #pragma unroll
        for (int r = 0; r < RPT; ++r) xa[r] = xs[r][a];

        {   // degree-1: x_a
            u64 wp[NPAIRS];
            load_wrow(c1, wp);  c1 += WROW_B;
            #pragma unroll
            for (int r = 0; r < RPT; ++r) {
                const u64 t = dup2(xa[r]);
                #pragma unroll
                for (int p = 0; p < NPAIRS; ++p)
                    acc[r][p] = ffma2(t, wp[p], acc[r][p]);
            }
        }

        #pragma unroll 1
        for (int b = a; b < NVARS; ++b) {
            float pab[RPT];
            #pragma unroll
            for (int r = 0; r < RPT; ++r) pab[r] = xa[r] * xs[r][b];

            {   // degree-2: x_a x_b
                u64 wp[NPAIRS];
                load_wrow(c2, wp);  c2 += WROW_B;
                #pragma unroll
                for (int r = 0; r < RPT; ++r) {
                    const u64 t = dup2(pab[r]);
                    #pragma unroll
                    for (int p = 0; p < NPAIRS; ++p)
                        acc[r][p] = ffma2(t, wp[p], acc[r][p]);
                }
            }

            #pragma unroll 1
            for (int c = b; c < NVARS; ++c) {
                // degree-3: x_a x_b x_c
                u64 wp[NPAIRS];
                load_wrow(c3, wp);  c3 += WROW_B;
                #pragma unroll
                for (int r = 0; r < RPT; ++r) {
                    const u64 t = dup2(pab[r] * xs[r][c]);
                    #pragma unroll
                    for (int p = 0; p < NPAIRS; ++p)
                        acc[r][p] = ffma2(t, wp[p], acc[r][p]);
                }
            }
        }
    }

    // Output pairs are contiguous (row stride 72 B, 8-byte aligned).
    #pragma unroll
    for (int r = 0; r < RPT; ++r) {
        u64* orow = reinterpret_cast<u64*>(out + (size_t)(base + r) * NVARS);
        if (STORE_DIRECT) {
            #pragma unroll
            for (int p = 0; p < NPAIRS; ++p) orow[p] = acc[r][p];
        } else {
            #pragma unroll
            for (int p = 0; p < NPAIRS; ++p) orow[p] = fadd2(acc[r][p], orow[p]);
        }
    }
}

// Piece table (contiguous prefix slices of the deg1/deg2/deg3 sections):
//  P1 a[0,2):  N=(2,35,324)  G=(1,19,190)    rows 361+bias  SMEM 28960
//  P2 a[2,4):  N=(2,31,256)  G=(3,54,514)    rows 289       SMEM 23200
//  P3 a[4,7):  N=(3,39,274)  G=(5,85,770)    rows 316       SMEM 25360
//  P4 a[7,18): N=(11,66,286) G=(8,124,1044)  rows 363       SMEM 29120
#define SMEM_P1 ((1 + 2 + 35 + 324) * WROW_B)
#define SMEM_P2 ((1 + 2 + 31 + 256) * WROW_B)
#define SMEM_P3 ((1 + 3 + 39 + 274) * WROW_B)
#define SMEM_P4 ((1 + 11 + 66 + 286) * WROW_B)

extern "C" void kernel_launch(void* const* d_in, const int* in_sizes, int n_in,
                              void* d_out, int out_size)
{
    const float* z      = (const float*)d_in[0];
    const float* betas  = (const float*)d_in[1];
    const float* big_xi = (const float*)d_in[2];
    const float* mask   = (const float*)d_in[3];
    float* out = (float*)d_out;

    auto k1 = vindy_piece<0, 2, 2, 35, 324, 1, 19, 190, true,  true>;
    auto k2 = vindy_piece<2, 4, 2, 31, 256, 3, 54, 514, false, false>;
    auto k3 = vindy_piece<4, 7, 3, 39, 274, 5, 85, 770, false, false>;
    auto k4 = vindy_piece<7, 18, 11, 66, 286, 8, 124, 1044, false, false>;

    cudaFuncSetAttribute(k1, cudaFuncAttributeMaxDynamicSharedMemorySize, SMEM_P1);
    cudaFuncSetAttribute(k2, cudaFuncAttributeMaxDynamicSharedMemorySize, SMEM_P2);
    cudaFuncSetAttribute(k3, cudaFuncAttributeMaxDynamicSharedMemorySize, SMEM_P3);
    cudaFuncSetAttribute(k4, cudaFuncAttributeMaxDynamicSharedMemorySize, SMEM_P4);

    const int grid = BATCH_N / (RPT * TPB);   // 512 blocks per launch
    k1<<<grid, TPB, SMEM_P1>>>(z, betas, big_xi, mask, out);
    k2<<<grid, TPB, SMEM_P2>>>(z, betas, big_xi, mask, out);
    k3<<<grid, TPB, SMEM_P3>>>(z, betas, big_xi, mask, out);
    k4<<<grid, TPB, SMEM_P4>>>(z, betas, big_xi, mask, out);
}